// round 3
// baseline (speedup 1.0000x reference)
#include <cuda_runtime.h>
#include <math.h>

#define BD   2
#define SEQ  1024
#define DM   768
#define NH   12
#define HD   64
#define GD   192
#define ATT_SCALE 0.125f

// ------------------------------ scratch ------------------------------------
__device__ float g_qw[BD*NH*SEQ*HD];
__device__ float g_qr[BD*NH*SEQ*HD];
__device__ float g_k [BD*NH*SEQ*HD];
__device__ float g_v [BD*NH*SEQ*HD];
__device__ float g_rh[NH*2048*HD];
__device__ float g_av[BD*SEQ*DM];
__device__ float g_h [BD*SEQ*DM];

__device__ __forceinline__ int SW(int kk, int idx) {
    return idx ^ (((kk >> 2) & 7) << 2);
}

// ---------------------------------------------------------------------------
// K1: grouped QKV projection.  grid (32, 12, 3)
// ---------------------------------------------------------------------------
__global__ void __launch_bounds__(256) qkv_kernel(
    const float* __restrict__ x,
    const float* __restrict__ Wq, const float* __restrict__ Wk, const float* __restrict__ bk,
    const float* __restrict__ Wv, const float* __restrict__ bv,
    const float* __restrict__ rwb, const float* __restrict__ rrb)
{
    __shared__ float sA[16][65];
    __shared__ float sB[16][64];
    const int m0  = blockIdx.x * 64;
    const int g   = blockIdx.y / 3, oo0 = (blockIdx.y % 3) * 64;
    const int z   = blockIdx.z;
    const float* W  = ((z == 0) ? Wq : (z == 1) ? Wk : Wv) + g * GD * GD;
    const float* xg = x + (size_t)m0 * DM + g * GD;
    const int tid = threadIdx.x, tx = tid & 15, ty = tid >> 4;
    const int la_k = tid & 15, la_m = tid >> 4;
    float acc[4][4] = {};

    for (int kb = 0; kb < GD; kb += 16) {
        #pragma unroll
        for (int r = 0; r < 4; r++)
            sA[la_k][la_m + r*16] = xg[(size_t)(la_m + r*16) * DM + kb + la_k];
        *(float4*)&sB[la_m][la_k*4] =
            *(const float4*)&W[(size_t)(kb + la_m) * GD + oo0 + la_k*4];
        __syncthreads();
        #pragma unroll
        for (int kk = 0; kk < 16; kk++) {
            float a[4];
            #pragma unroll
            for (int q = 0; q < 4; q++) a[q] = sA[kk][ty*4 + q];
            float4 b4 = *(float4*)&sB[kk][tx*4];
            #pragma unroll
            for (int di = 0; di < 4; di++) {
                acc[di][0] += a[di]*b4.x; acc[di][1] += a[di]*b4.y;
                acc[di][2] += a[di]*b4.z; acc[di][3] += a[di]*b4.w;
            }
        }
        __syncthreads();
    }

    const int o0 = g*GD + oo0;
    const int n  = o0 >> 6, d0 = tx*4;
    #pragma unroll
    for (int di = 0; di < 4; di++) {
        int m = m0 + ty*4 + di;
        int b = m >> 10, s = m & 1023;
        size_t ob = (((size_t)(b*NH + n))*SEQ + s)*HD + d0;
        if (z == 0) {
            float4 vw, vr;
            vw.x = (acc[di][0] + rwb[o0+d0+0]) * ATT_SCALE;
            vw.y = (acc[di][1] + rwb[o0+d0+1]) * ATT_SCALE;
            vw.z = (acc[di][2] + rwb[o0+d0+2]) * ATT_SCALE;
            vw.w = (acc[di][3] + rwb[o0+d0+3]) * ATT_SCALE;
            vr.x = (acc[di][0] + rrb[o0+d0+0]) * ATT_SCALE;
            vr.y = (acc[di][1] + rrb[o0+d0+1]) * ATT_SCALE;
            vr.z = (acc[di][2] + rrb[o0+d0+2]) * ATT_SCALE;
            vr.w = (acc[di][3] + rrb[o0+d0+3]) * ATT_SCALE;
            *(float4*)&g_qw[ob] = vw;
            *(float4*)&g_qr[ob] = vr;
        } else if (z == 1) {
            float4 v;
            v.x = acc[di][0]+bk[o0+d0+0]; v.y = acc[di][1]+bk[o0+d0+1];
            v.z = acc[di][2]+bk[o0+d0+2]; v.w = acc[di][3]+bk[o0+d0+3];
            *(float4*)&g_k[ob] = v;
        } else {
            float4 v;
            v.x = acc[di][0]+bv[o0+d0+0]; v.y = acc[di][1]+bv[o0+d0+1];
            v.z = acc[di][2]+bv[o0+d0+2]; v.w = acc[di][3]+bv[o0+d0+3];
            *(float4*)&g_v[ob] = v;
        }
    }
}

// ---------------------------------------------------------------------------
// K2: r_head = position_embeds @ r_kernel.  grid (32, 12)
// ---------------------------------------------------------------------------
__global__ void __launch_bounds__(256) rhead_kernel(
    const float* __restrict__ pe, const float* __restrict__ rk)
{
    __shared__ float sA[16][65];
    __shared__ float sB[16][64];
    const int t0b = blockIdx.x * 64;
    const int o0  = blockIdx.y * 64;
    const int tid = threadIdx.x, tx = tid & 15, ty = tid >> 4;
    const int la_k = tid & 15, la_m = tid >> 4;
    float acc[4][4] = {};

    for (int kb = 0; kb < DM; kb += 16) {
        #pragma unroll
        for (int r = 0; r < 4; r++) {
            int t = t0b + la_m + r*16;
            sA[la_k][la_m + r*16] = (t < 2047) ? pe[(size_t)t * DM + kb + la_k] : 0.f;
        }
        *(float4*)&sB[la_m][la_k*4] =
            *(const float4*)&rk[(size_t)(kb + la_m) * DM + o0 + la_k*4];
        __syncthreads();
        #pragma unroll
        for (int kk = 0; kk < 16; kk++) {
            float a[4];
            #pragma unroll
            for (int q = 0; q < 4; q++) a[q] = sA[kk][ty*4 + q];
            float4 b4 = *(float4*)&sB[kk][tx*4];
            #pragma unroll
            for (int di = 0; di < 4; di++) {
                acc[di][0] += a[di]*b4.x; acc[di][1] += a[di]*b4.y;
                acc[di][2] += a[di]*b4.z; acc[di][3] += a[di]*b4.w;
            }
        }
        __syncthreads();
    }
    const int n = o0 >> 6, d0 = tx*4;
    #pragma unroll
    for (int di = 0; di < 4; di++) {
        int t = t0b + ty*4 + di;
        float4 v = make_float4(acc[di][0], acc[di][1], acc[di][2], acc[di][3]);
        *(float4*)&g_rh[((size_t)n*2048 + t)*HD + d0] = v;
    }
}

// ---------------------------------------------------------------------------
// K3: flash attention with banded relative positions. grid (16, 24)
// ---------------------------------------------------------------------------
#define ATTN_SMEM_FLOATS (4096*3 + 8192 + 64*65 + 4096)
#define ATTN_SMEM_BYTES  (ATTN_SMEM_FLOATS * 4)

__global__ void __launch_bounds__(256, 1) attn_kernel()
{
    extern __shared__ float sm[];
    float* sQw = sm;
    float* sQr = sm + 4096;
    float* sKT = sm + 8192;
    float* sRh = sm + 12288;            // [64 d][128 u]
    float* sPT = sm + 20480;            // [64 jj][65 ii]
    float* sV  = sm + 20480 + 64*65;    // [64 jj][64 dd]

    const int bn = blockIdx.y;
    const int n  = bn % NH;
    const int i0 = blockIdx.x * 64;
    const int tid = threadIdx.x, tx = tid & 15, ty = tid >> 4;

    const float* qwB = g_qw + (size_t)bn * SEQ * HD;
    const float* qrB = g_qr + (size_t)bn * SEQ * HD;
    const float* kB  = g_k  + (size_t)bn * SEQ * HD;
    const float* vB  = g_v  + (size_t)bn * SEQ * HD;
    const float* rhB = g_rh + (size_t)n * 2048 * HD;

    const int lr  = tid >> 4;
    const int ldc = (tid & 15) * 4;

    #pragma unroll
    for (int r = 0; r < 4; r++) {
        int ii = lr + r*16;
        float4 a = *(const float4*)&qwB[(size_t)(i0+ii)*HD + ldc];
        float4 b = *(const float4*)&qrB[(size_t)(i0+ii)*HD + ldc];
        sQw[(ldc+0)*64 + SW(ldc+0, ii)] = a.x;
        sQw[(ldc+1)*64 + SW(ldc+1, ii)] = a.y;
        sQw[(ldc+2)*64 + SW(ldc+2, ii)] = a.z;
        sQw[(ldc+3)*64 + SW(ldc+3, ii)] = a.w;
        sQr[(ldc+0)*64 + SW(ldc+0, ii)] = b.x;
        sQr[(ldc+1)*64 + SW(ldc+1, ii)] = b.y;
        sQr[(ldc+2)*64 + SW(ldc+2, ii)] = b.z;
        sQr[(ldc+3)*64 + SW(ldc+3, ii)] = b.w;
    }

    float m_i[4], l_i[4], oacc[4][4];
    #pragma unroll
    for (int di = 0; di < 4; di++) {
        m_i[di] = -INFINITY; l_i[di] = 0.f;
        #pragma unroll
        for (int q = 0; q < 4; q++) oacc[di][q] = 0.f;
    }
    const int u0 = 63 + 4*(tx - ty);

    for (int j0 = 0; j0 < SEQ; j0 += 64) {
        __syncthreads();
        #pragma unroll
        for (int r = 0; r < 4; r++) {
            int jj = lr + r*16;
            float4 kv = *(const float4*)&kB[(size_t)(j0+jj)*HD + ldc];
            sKT[(ldc+0)*64 + SW(ldc+0, jj)] = kv.x;
            sKT[(ldc+1)*64 + SW(ldc+1, jj)] = kv.y;
            sKT[(ldc+2)*64 + SW(ldc+2, jj)] = kv.z;
            sKT[(ldc+3)*64 + SW(ldc+3, jj)] = kv.w;
            *(float4*)&sV[jj*64 + ldc] = *(const float4*)&vB[(size_t)(j0+jj)*HD + ldc];
        }
        const int t0 = 961 + j0 - i0;
        #pragma unroll
        for (int r = 0; r < 8; r++) {
            int u = lr + r*16;
            int t = t0 + u;
            float4 rv = make_float4(0.f,0.f,0.f,0.f);
            if (t >= 0 && t <= 2046)
                rv = *(const float4*)&rhB[(size_t)t*HD + ldc];
            sRh[(ldc+0)*128 + SW(ldc+0, u)] = rv.x;
            sRh[(ldc+1)*128 + SW(ldc+1, u)] = rv.y;
            sRh[(ldc+2)*128 + SW(ldc+2, u)] = rv.z;
            sRh[(ldc+3)*128 + SW(ldc+3, u)] = rv.w;
        }
        __syncthreads();

        float acc[4][4] = {};
        #pragma unroll 4
        for (int kk = 0; kk < 64; kk++) {
            float4 aw = *(float4*)&sQw[kk*64  + SW(kk, ty*4)];
            float4 ar = *(float4*)&sQr[kk*64  + SW(kk, ty*4)];
            float4 b4 = *(float4*)&sKT[kk*64  + SW(kk, tx*4)];
            float4 r0 = *(float4*)&sRh[kk*128 + SW(kk, u0-3)];
            float4 r1 = *(float4*)&sRh[kk*128 + SW(kk, u0+1)];
            float A[4]  = {aw.x, aw.y, aw.z, aw.w};
            float R[4]  = {ar.x, ar.y, ar.z, ar.w};
            float Bk[4] = {b4.x, b4.y, b4.z, b4.w};
            float br[8] = {r0.x, r0.y, r0.z, r0.w, r1.x, r1.y, r1.z, r1.w};
            #pragma unroll
            for (int di = 0; di < 4; di++) {
                #pragma unroll
                for (int dj = 0; dj < 4; dj++)
                    acc[di][dj] += A[di]*Bk[dj] + R[di]*br[3 + dj - di];
            }
        }
        // HF rel-shift wrap quirk: out[0][1023] = qr[1] . r_head[0]
        if (i0 == 0 && j0 == 960 && tid == 15) {
            float s = 0.f;
            #pragma unroll
            for (int d = 0; d < HD; d++) s += qrB[HD + d] * rhB[d];
            acc[0][3] += s;
        }

        // online softmax
        float p[4][4];
        #pragma unroll
        for (int di = 0; di < 4; di++) {
            float mx = fmaxf(fmaxf(acc[di][0], acc[di][1]), fmaxf(acc[di][2], acc[di][3]));
            #pragma unroll
            for (int o = 1; o < 16; o <<= 1)
                mx = fmaxf(mx, __shfl_xor_sync(0xffffffffu, mx, o));
            float m_new = fmaxf(m_i[di], mx);
            float sc = __expf(m_i[di] - m_new);
            float rs = 0.f;
            #pragma unroll
            for (int dj = 0; dj < 4; dj++) {
                p[di][dj] = __expf(acc[di][dj] - m_new);
                rs += p[di][dj];
            }
            #pragma unroll
            for (int o = 1; o < 16; o <<= 1)
                rs += __shfl_xor_sync(0xffffffffu, rs, o);
            l_i[di] = l_i[di]*sc + rs;
            m_i[di] = m_new;
            #pragma unroll
            for (int q = 0; q < 4; q++) oacc[di][q] *= sc;
        }
        #pragma unroll
        for (int di = 0; di < 4; di++)
            #pragma unroll
            for (int dj = 0; dj < 4; dj++)
                sPT[(tx*4+dj)*65 + ty*4+di] = p[di][dj];
        __syncthreads();

        #pragma unroll 4
        for (int jj = 0; jj < 64; jj++) {
            float a[4];
            #pragma unroll
            for (int di = 0; di < 4; di++) a[di] = sPT[jj*65 + ty*4+di];
            float4 v4 = *(float4*)&sV[jj*64 + tx*4];
            #pragma unroll
            for (int di = 0; di < 4; di++) {
                oacc[di][0] += a[di]*v4.x; oacc[di][1] += a[di]*v4.y;
                oacc[di][2] += a[di]*v4.z; oacc[di][3] += a[di]*v4.w;
            }
        }
    }

    const int b = bn / NH;
    #pragma unroll
    for (int di = 0; di < 4; di++) {
        float inv = 1.f / l_i[di];
        int i = i0 + ty*4 + di;
        float4 v = make_float4(oacc[di][0]*inv, oacc[di][1]*inv,
                               oacc[di][2]*inv, oacc[di][3]*inv);
        *(float4*)&g_av[((size_t)(b*SEQ + i))*DM + n*HD + tx*4] = v;
    }
}

// ---------------------------------------------------------------------------
// K4: h = query + av @ Wo + bo.  grid (32, 12)
// ---------------------------------------------------------------------------
__global__ void __launch_bounds__(256) proj_kernel(
    const float* __restrict__ Wo, const float* __restrict__ bo,
    const float* __restrict__ x)
{
    __shared__ float sA[16][65];
    __shared__ float sB[16][64];
    const int m0 = blockIdx.x * 64;
    const int o0 = blockIdx.y * 64;
    const int tid = threadIdx.x, tx = tid & 15, ty = tid >> 4;
    const int la_k = tid & 15, la_m = tid >> 4;
    float acc[4][4] = {};

    for (int kb = 0; kb < DM; kb += 16) {
        #pragma unroll
        for (int r = 0; r < 4; r++)
            sA[la_k][la_m + r*16] = g_av[(size_t)(m0 + la_m + r*16) * DM + kb + la_k];
        *(float4*)&sB[la_m][la_k*4] =
            *(const float4*)&Wo[(size_t)(kb + la_m) * DM + o0 + la_k*4];
        __syncthreads();
        #pragma unroll
        for (int kk = 0; kk < 16; kk++) {
            float a[4];
            #pragma unroll
            for (int q = 0; q < 4; q++) a[q] = sA[kk][ty*4 + q];
            float4 b4 = *(float4*)&sB[kk][tx*4];
            #pragma unroll
            for (int di = 0; di < 4; di++) {
                acc[di][0] += a[di]*b4.x; acc[di][1] += a[di]*b4.y;
                acc[di][2] += a[di]*b4.z; acc[di][3] += a[di]*b4.w;
            }
        }
        __syncthreads();
    }
    const int d0 = tx*4;
    #pragma unroll
    for (int di = 0; di < 4; di++) {
        int m = m0 + ty*4 + di;
        size_t ob = (size_t)m * DM + o0 + d0;
        float4 qv = *(const float4*)&x[ob];
        float4 v;
        v.x = acc[di][0] + bo[o0+d0+0] + qv.x;
        v.y = acc[di][1] + bo[o0+d0+1] + qv.y;
        v.z = acc[di][2] + bo[o0+d0+2] + qv.z;
        v.w = acc[di][3] + bo[o0+d0+3] + qv.w;
        *(float4*)&g_h[ob] = v;
    }
}

// ---------------------------------------------------------------------------
// K5: LayerNorm.  grid (2048), 256 threads
// ---------------------------------------------------------------------------
__global__ void __launch_bounds__(256) ln_kernel(
    const float* __restrict__ gamma, const float* __restrict__ beta,
    float* __restrict__ out)
{
    __shared__ float red[16];
    const int row = blockIdx.x;
    const int tid = threadIdx.x;
    const float* h = g_h + (size_t)row * DM;
    float v0 = h[tid], v1 = h[tid+256], v2 = h[tid+512];
    float s = v0+v1+v2, ss = v0*v0+v1*v1+v2*v2;
    #pragma unroll
    for (int o = 16; o >= 1; o >>= 1) {
        s  += __shfl_xor_sync(0xffffffffu, s,  o);
        ss += __shfl_xor_sync(0xffffffffu, ss, o);
    }
    if ((tid & 31) == 0) { red[tid>>5] = s; red[8 + (tid>>5)] = ss; }
    __syncthreads();
    if (tid < 32) {
        float a = (tid < 8)  ? red[tid]     : 0.f;
        float b = (tid < 8)  ? red[8+tid]   : 0.f;
        #pragma unroll
        for (int o = 4; o >= 1; o >>= 1) {
            a += __shfl_xor_sync(0xffffffffu, a, o);
            b += __shfl_xor_sync(0xffffffffu, b, o);
        }
        if (tid == 0) { red[0] = a; red[1] = b; }
    }
    __syncthreads();
    float mu  = red[0] * (1.f/DM);
    float var = red[1] * (1.f/DM) - mu*mu;
    float inv = rsqrtf(var + 1e-9f);
    out[(size_t)row*DM + tid]     = (v0 - mu)*inv*gamma[tid]     + beta[tid];
    out[(size_t)row*DM + tid+256] = (v1 - mu)*inv*gamma[tid+256] + beta[tid+256];
    out[(size_t)row*DM + tid+512] = (v2 - mu)*inv*gamma[tid+512] + beta[tid+512];
}

// ---------------------------------------------------------------------------
extern "C" void kernel_launch(void* const* d_in, const int* in_sizes, int n_in,
                              void* d_out, int out_size)
{
    const float* query = (const float*)d_in[0];
    const float* pe    = (const float*)d_in[1];
    const float* Wq    = (const float*)d_in[2];
    const float* Wk    = (const float*)d_in[3];
    const float* bk    = (const float*)d_in[4];
    const float* Wv    = (const float*)d_in[5];
    const float* bv    = (const float*)d_in[6];
    const float* rk    = (const float*)d_in[7];
    const float* rwb   = (const float*)d_in[8];
    const float* rrb   = (const float*)d_in[9];
    const float* Wo    = (const float*)d_in[10];
    const float* bo    = (const float*)d_in[11];
    const float* gamma = (const float*)d_in[12];
    const float* beta  = (const float*)d_in[13];
    float* out = (float*)d_out;

    static bool attr_set = false;
    if (!attr_set) {
        cudaFuncSetAttribute(attn_kernel,
            cudaFuncAttributeMaxDynamicSharedMemorySize, ATTN_SMEM_BYTES);
        attr_set = true;
    }

    qkv_kernel<<<dim3(32,12,3), 256>>>(query, Wq, Wk, bk, Wv, bv, rwb, rrb);
    rhead_kernel<<<dim3(32,12), 256>>>(pe, rk);
    attn_kernel<<<dim3(16,24), 256, ATTN_SMEM_BYTES>>>();
    proj_kernel<<<dim3(32,12), 256>>>(Wo, bo, query);
    ln_kernel<<<2048, 256>>>(gamma, beta, out);
}

// round 4
// speedup vs baseline: 2.2745x; 2.2745x over previous
#include <cuda_runtime.h>
#include <cuda_bf16.h>
#include <math.h>

#define BD   2
#define SEQ  1024
#define DM   768
#define NH   12
#define HD   64
#define GD   192
#define ATT_SCALE 0.125f

typedef __nv_bfloat16 bf16;

// ------------------------------ scratch ------------------------------------
__device__ __align__(16) bf16 g_qw[BD*NH*SEQ*HD];
__device__ __align__(16) bf16 g_qr[BD*NH*SEQ*HD];
__device__ __align__(16) bf16 g_k [BD*NH*SEQ*HD];
__device__ __align__(16) bf16 g_v [BD*NH*SEQ*HD];
__device__ __align__(16) bf16 g_rh[NH*2048*HD];
__device__ float g_av[BD*SEQ*DM];
__device__ float g_h [BD*SEQ*DM];

// pack two fp32 -> bf16x2 (lo in low half)
__device__ __forceinline__ unsigned pk(float lo, float hi) {
    __nv_bfloat162 h = __floats2bfloat162_rn(lo, hi);
    return *(unsigned*)&h;
}
__device__ __forceinline__ unsigned s2u(const void* p) {
    return (unsigned)__cvta_generic_to_shared(p);
}
__device__ __forceinline__ void ldm_x4(unsigned& r0, unsigned& r1, unsigned& r2, unsigned& r3, unsigned a) {
    asm volatile("ldmatrix.sync.aligned.m8n8.x4.shared.b16 {%0,%1,%2,%3},[%4];"
                 : "=r"(r0), "=r"(r1), "=r"(r2), "=r"(r3) : "r"(a));
}
__device__ __forceinline__ void ldm_x2(unsigned& r0, unsigned& r1, unsigned a) {
    asm volatile("ldmatrix.sync.aligned.m8n8.x2.shared.b16 {%0,%1},[%2];"
                 : "=r"(r0), "=r"(r1) : "r"(a));
}
__device__ __forceinline__ void ldm_x2t(unsigned& r0, unsigned& r1, unsigned a) {
    asm volatile("ldmatrix.sync.aligned.m8n8.x2.trans.shared.b16 {%0,%1},[%2];"
                 : "=r"(r0), "=r"(r1) : "r"(a));
}
__device__ __forceinline__ void mma_bf16(float* c, const unsigned* a, unsigned b0, unsigned b1) {
    asm volatile("mma.sync.aligned.m16n8k16.row.col.f32.bf16.bf16.f32 "
                 "{%0,%1,%2,%3},{%4,%5,%6,%7},{%8,%9},{%0,%1,%2,%3};"
                 : "+f"(c[0]), "+f"(c[1]), "+f"(c[2]), "+f"(c[3])
                 : "r"(a[0]), "r"(a[1]), "r"(a[2]), "r"(a[3]), "r"(b0), "r"(b1));
}

// ---------------------------------------------------------------------------
// K1: grouped QKV projection (fp32 compute, bf16 store).  grid (32, 12, 3)
// ---------------------------------------------------------------------------
__global__ void __launch_bounds__(256) qkv_kernel(
    const float* __restrict__ x,
    const float* __restrict__ Wq, const float* __restrict__ Wk, const float* __restrict__ bk,
    const float* __restrict__ Wv, const float* __restrict__ bv,
    const float* __restrict__ rwb, const float* __restrict__ rrb)
{
    __shared__ float sA[16][65];
    __shared__ float sB[16][64];
    const int m0  = blockIdx.x * 64;
    const int g   = blockIdx.y / 3, oo0 = (blockIdx.y % 3) * 64;
    const int z   = blockIdx.z;
    const float* W  = ((z == 0) ? Wq : (z == 1) ? Wk : Wv) + g * GD * GD;
    const float* xg = x + (size_t)m0 * DM + g * GD;
    const int tid = threadIdx.x, tx = tid & 15, ty = tid >> 4;
    const int la_k = tid & 15, la_m = tid >> 4;
    float acc[4][4] = {};

    for (int kb = 0; kb < GD; kb += 16) {
        #pragma unroll
        for (int r = 0; r < 4; r++)
            sA[la_k][la_m + r*16] = xg[(size_t)(la_m + r*16) * DM + kb + la_k];
        *(float4*)&sB[la_m][la_k*4] =
            *(const float4*)&W[(size_t)(kb + la_m) * GD + oo0 + la_k*4];
        __syncthreads();
        #pragma unroll
        for (int kk = 0; kk < 16; kk++) {
            float a[4];
            #pragma unroll
            for (int q = 0; q < 4; q++) a[q] = sA[kk][ty*4 + q];
            float4 b4 = *(float4*)&sB[kk][tx*4];
            #pragma unroll
            for (int di = 0; di < 4; di++) {
                acc[di][0] += a[di]*b4.x; acc[di][1] += a[di]*b4.y;
                acc[di][2] += a[di]*b4.z; acc[di][3] += a[di]*b4.w;
            }
        }
        __syncthreads();
    }

    const int o0 = g*GD + oo0;
    const int n  = o0 >> 6, d0 = tx*4;
    #pragma unroll
    for (int di = 0; di < 4; di++) {
        int m = m0 + ty*4 + di;
        int b = m >> 10, s = m & 1023;
        size_t ob = (((size_t)(b*NH + n))*SEQ + s)*HD + d0;
        if (z == 0) {
            *(unsigned*)&g_qw[ob]   = pk((acc[di][0]+rwb[o0+d0+0])*ATT_SCALE,
                                         (acc[di][1]+rwb[o0+d0+1])*ATT_SCALE);
            *(unsigned*)&g_qw[ob+2] = pk((acc[di][2]+rwb[o0+d0+2])*ATT_SCALE,
                                         (acc[di][3]+rwb[o0+d0+3])*ATT_SCALE);
            *(unsigned*)&g_qr[ob]   = pk((acc[di][0]+rrb[o0+d0+0])*ATT_SCALE,
                                         (acc[di][1]+rrb[o0+d0+1])*ATT_SCALE);
            *(unsigned*)&g_qr[ob+2] = pk((acc[di][2]+rrb[o0+d0+2])*ATT_SCALE,
                                         (acc[di][3]+rrb[o0+d0+3])*ATT_SCALE);
        } else if (z == 1) {
            *(unsigned*)&g_k[ob]   = pk(acc[di][0]+bk[o0+d0+0], acc[di][1]+bk[o0+d0+1]);
            *(unsigned*)&g_k[ob+2] = pk(acc[di][2]+bk[o0+d0+2], acc[di][3]+bk[o0+d0+3]);
        } else {
            *(unsigned*)&g_v[ob]   = pk(acc[di][0]+bv[o0+d0+0], acc[di][1]+bv[o0+d0+1]);
            *(unsigned*)&g_v[ob+2] = pk(acc[di][2]+bv[o0+d0+2], acc[di][3]+bv[o0+d0+3]);
        }
    }
}

// ---------------------------------------------------------------------------
// K2: r_head = position_embeds @ r_kernel (bf16 store).  grid (32, 12)
// ---------------------------------------------------------------------------
__global__ void __launch_bounds__(256) rhead_kernel(
    const float* __restrict__ pe, const float* __restrict__ rk)
{
    __shared__ float sA[16][65];
    __shared__ float sB[16][64];
    const int t0b = blockIdx.x * 64;
    const int o0  = blockIdx.y * 64;
    const int tid = threadIdx.x, tx = tid & 15, ty = tid >> 4;
    const int la_k = tid & 15, la_m = tid >> 4;
    float acc[4][4] = {};

    for (int kb = 0; kb < DM; kb += 16) {
        #pragma unroll
        for (int r = 0; r < 4; r++) {
            int t = t0b + la_m + r*16;
            sA[la_k][la_m + r*16] = (t < 2047) ? pe[(size_t)t * DM + kb + la_k] : 0.f;
        }
        *(float4*)&sB[la_m][la_k*4] =
            *(const float4*)&rk[(size_t)(kb + la_m) * DM + o0 + la_k*4];
        __syncthreads();
        #pragma unroll
        for (int kk = 0; kk < 16; kk++) {
            float a[4];
            #pragma unroll
            for (int q = 0; q < 4; q++) a[q] = sA[kk][ty*4 + q];
            float4 b4 = *(float4*)&sB[kk][tx*4];
            #pragma unroll
            for (int di = 0; di < 4; di++) {
                acc[di][0] += a[di]*b4.x; acc[di][1] += a[di]*b4.y;
                acc[di][2] += a[di]*b4.z; acc[di][3] += a[di]*b4.w;
            }
        }
        __syncthreads();
    }
    const int n = o0 >> 6, d0 = tx*4;
    #pragma unroll
    for (int di = 0; di < 4; di++) {
        int t = t0b + ty*4 + di;
        size_t ob = ((size_t)n*2048 + t)*HD + d0;
        *(unsigned*)&g_rh[ob]   = pk(acc[di][0], acc[di][1]);
        *(unsigned*)&g_rh[ob+2] = pk(acc[di][2], acc[di][3]);
    }
}

// ---------------------------------------------------------------------------
// K3: flash attention, bf16 HMMA, pos' sliding-window ring. grid (16, 24), 128 thr
// ---------------------------------------------------------------------------
#define RING_PITCH 132
#define ATT_SMEM_BYTES (40960 + 64*RING_PITCH*4)   // 5 bf16 tiles + fp32 ring

__device__ __forceinline__ void copy_tile64(bf16* dst, const bf16* src, int tid) {
    #pragma unroll
    for (int k = 0; k < 4; k++) {
        int c = tid + k*128, row = c >> 3, ch = c & 7;
        uint4 v = *(const uint4*)(src + (size_t)row*64 + ch*8);
        *(uint4*)((char*)dst + row*128 + ((ch ^ (row & 7)) << 4)) = v;
    }
}
__device__ __forceinline__ void load_rh_tile(bf16* dst, const bf16* src, int Tc, int tid) {
    #pragma unroll
    for (int k = 0; k < 4; k++) {
        int c = tid + k*128, row = c >> 3, ch = c & 7;
        int t = Tc + row;
        uint4 v = make_uint4(0u,0u,0u,0u);
        if (t < 2048) v = *(const uint4*)(src + (size_t)t*64 + ch*8);
        *(uint4*)((char*)dst + row*128 + ((ch ^ (row & 7)) << 4)) = v;
    }
}

__device__ __forceinline__ void pos_mma_ring(
    const bf16* sRh, float* ring, const unsigned (*qrA)[4],
    int Tc, int lane, int r0, int q2)
{
    #pragma unroll
    for (int nb = 0; nb < 8; nb++) {
        float pc[4] = {0.f, 0.f, 0.f, 0.f};
        int brow = nb*8 + (lane & 7);
        #pragma unroll
        for (int ks = 0; ks < 4; ks++) {
            int ch = ks*2 + ((lane >> 3) & 1);
            unsigned b0, b1;
            ldm_x2(b0, b1, s2u((const char*)sRh + brow*128 + ((ch ^ (brow & 7)) << 4)));
            mma_bf16(pc, qrA[ks], b0, b1);
        }
        int s0 = (Tc + nb*8 + q2) & 127;
        int s1 = (s0 + 1) & 127;
        ring[r0*RING_PITCH + s0]     = pc[0];
        ring[r0*RING_PITCH + s1]     = pc[1];
        ring[(r0+8)*RING_PITCH + s0] = pc[2];
        ring[(r0+8)*RING_PITCH + s1] = pc[3];
    }
}

__global__ void __launch_bounds__(128) attn_kernel()
{
    extern __shared__ char smc[];
    bf16*  sQw  = (bf16*)(smc);
    bf16*  sQr  = (bf16*)(smc + 8192);
    bf16*  sK   = (bf16*)(smc + 16384);
    bf16*  sRh  = (bf16*)(smc + 24576);
    bf16*  sV   = (bf16*)(smc + 32768);
    float* ring = (float*)(smc + 40960);

    const int tid = threadIdx.x, lane = tid & 31, w = tid >> 5;
    const int bn = blockIdx.y, n = bn % NH, b = bn / NH;
    const int i0 = blockIdx.x * 64;

    const bf16* qwB = g_qw + (size_t)bn * SEQ * HD;
    const bf16* qrB = g_qr + (size_t)bn * SEQ * HD;
    const bf16* kB  = g_k  + (size_t)bn * SEQ * HD;
    const bf16* vB  = g_v  + (size_t)bn * SEQ * HD;
    const bf16* rhB = g_rh + (size_t)n * 2048 * HD;

    copy_tile64(sQw, qwB + (size_t)i0*HD, tid);
    copy_tile64(sQr, qrB + (size_t)i0*HD, tid);
    load_rh_tile(sRh, rhB, 961 - i0, tid);
    __syncthreads();

    // hoisted A-fragments for qw and qr (rows 16w..16w+15)
    unsigned qwA[4][4], qrA[4][4];
    {
        int arow = w*16 + (lane & 15);
        int csel = lane >> 4;
        #pragma unroll
        for (int ks = 0; ks < 4; ks++) {
            int ch = ks*2 + csel;
            unsigned off = ((ch ^ (arow & 7)) << 4) + arow*128;
            ldm_x4(qwA[ks][0], qwA[ks][1], qwA[ks][2], qwA[ks][3], s2u((char*)sQw + off));
            ldm_x4(qrA[ks][0], qrA[ks][1], qrA[ks][2], qrA[ks][3], s2u((char*)sQr + off));
        }
    }

    const int r0 = w*16 + (lane >> 2);
    const int q2 = 2*(lane & 3);

    float o[8][4] = {};
    float mrow0 = -INFINITY, mrow1 = -INFINITY, lrow0 = 0.f, lrow1 = 0.f;

    // first half of the pos' window
    pos_mma_ring(sRh, ring, qrA, 961 - i0, lane, r0, q2);

    for (int j0 = 0; j0 < SEQ; j0 += 64) {
        __syncthreads();    // protect sK/sV/sRh from previous iteration's readers
        copy_tile64(sK, kB + (size_t)j0*HD, tid);
        copy_tile64(sV, vB + (size_t)j0*HD, tid);
        const int Tc = 1025 + j0 - i0;        // new 64 pos' columns this iter
        load_rh_tile(sRh, rhB, Tc, tid);
        __syncthreads();

        // content scores: qw @ k^T
        float c[8][4] = {};
        #pragma unroll
        for (int nb = 0; nb < 8; nb++) {
            int brow = nb*8 + (lane & 7);
            #pragma unroll
            for (int ks = 0; ks < 4; ks++) {
                int ch = ks*2 + ((lane >> 3) & 1);
                unsigned b0, b1;
                ldm_x2(b0, b1, s2u((char*)sK + brow*128 + ((ch ^ (brow & 7)) << 4)));
                mma_bf16(c[nb], qwA[ks], b0, b1);
            }
        }
        // new pos' columns into the ring
        pos_mma_ring(sRh, ring, qrA, Tc, lane, r0, q2);
        __syncthreads();    // ring writes visible to all warps

        // gather positional band: t = 1024 + j - i
        #pragma unroll
        for (int nb = 0; nb < 8; nb++) {
            int jl = nb*8 + q2;
            int ta = 1024 + j0 + jl - (i0 + r0);
            c[nb][0] += ring[r0*RING_PITCH + (ta & 127)];
            c[nb][1] += ring[r0*RING_PITCH + ((ta + 1) & 127)];
            int tb = ta - 8;
            c[nb][2] += ring[(r0+8)*RING_PITCH + (tb & 127)];
            c[nb][3] += ring[(r0+8)*RING_PITCH + ((tb + 1) & 127)];
        }
        // HF rel-shift wrap quirk: score[0][1023] = content + qr[1].r_head[0]
        if (i0 == 0 && j0 == 960 && tid == 3) {
            float s = 0.f;
            #pragma unroll
            for (int d = 0; d < HD; d++)
                s += __bfloat162float(qrB[HD + d]) * __bfloat162float(rhB[d]);
            c[7][1] += s;   // (pos contribution was rh[2047] = 0)
        }

        // online softmax (rows r0 and r0+8, each spread over 4 lanes)
        float mx0 = -INFINITY, mx1 = -INFINITY;
        #pragma unroll
        for (int nb = 0; nb < 8; nb++) {
            mx0 = fmaxf(mx0, fmaxf(c[nb][0], c[nb][1]));
            mx1 = fmaxf(mx1, fmaxf(c[nb][2], c[nb][3]));
        }
        mx0 = fmaxf(mx0, __shfl_xor_sync(0xffffffffu, mx0, 1));
        mx0 = fmaxf(mx0, __shfl_xor_sync(0xffffffffu, mx0, 2));
        mx1 = fmaxf(mx1, __shfl_xor_sync(0xffffffffu, mx1, 1));
        mx1 = fmaxf(mx1, __shfl_xor_sync(0xffffffffu, mx1, 2));
        float mn0 = fmaxf(mrow0, mx0), mn1 = fmaxf(mrow1, mx1);
        float sc0 = __expf(mrow0 - mn0), sc1 = __expf(mrow1 - mn1);
        mrow0 = mn0; mrow1 = mn1;
        float s0 = 0.f, s1 = 0.f;
        #pragma unroll
        for (int nb = 0; nb < 8; nb++) {
            c[nb][0] = __expf(c[nb][0] - mn0); s0 += c[nb][0];
            c[nb][1] = __expf(c[nb][1] - mn0); s0 += c[nb][1];
            c[nb][2] = __expf(c[nb][2] - mn1); s1 += c[nb][2];
            c[nb][3] = __expf(c[nb][3] - mn1); s1 += c[nb][3];
        }
        s0 += __shfl_xor_sync(0xffffffffu, s0, 1);
        s0 += __shfl_xor_sync(0xffffffffu, s0, 2);
        s1 += __shfl_xor_sync(0xffffffffu, s1, 1);
        s1 += __shfl_xor_sync(0xffffffffu, s1, 2);
        lrow0 = lrow0*sc0 + s0; lrow1 = lrow1*sc1 + s1;
        #pragma unroll
        for (int nb = 0; nb < 8; nb++) {
            o[nb][0] *= sc0; o[nb][1] *= sc0;
            o[nb][2] *= sc1; o[nb][3] *= sc1;
        }

        // P (c-frag) -> A-frag bf16 repack
        unsigned pa[4][4];
        #pragma unroll
        for (int ks = 0; ks < 4; ks++) {
            pa[ks][0] = pk(c[2*ks][0],   c[2*ks][1]);
            pa[ks][1] = pk(c[2*ks][2],   c[2*ks][3]);
            pa[ks][2] = pk(c[2*ks+1][0], c[2*ks+1][1]);
            pa[ks][3] = pk(c[2*ks+1][2], c[2*ks+1][3]);
        }
        // o += P @ V  (V as B via ldmatrix.trans)
        #pragma unroll
        for (int nb = 0; nb < 8; nb++) {
            #pragma unroll
            for (int ks = 0; ks < 4; ks++) {
                int vrow = ks*16 + (lane & 15);
                unsigned b0, b1;
                ldm_x2t(b0, b1, s2u((char*)sV + vrow*128 + ((nb ^ (vrow & 7)) << 4)));
                mma_bf16(o[nb], pa[ks], b0, b1);
            }
        }
    }

    // epilogue
    float inv0 = 1.f / lrow0, inv1 = 1.f / lrow1;
    #pragma unroll
    for (int nb = 0; nb < 8; nb++) {
        int dd = nb*8 + q2;
        float2 v0 = make_float2(o[nb][0]*inv0, o[nb][1]*inv0);
        float2 v1 = make_float2(o[nb][2]*inv1, o[nb][3]*inv1);
        *(float2*)&g_av[((size_t)(b*SEQ + i0 + r0))*DM + n*HD + dd]     = v0;
        *(float2*)&g_av[((size_t)(b*SEQ + i0 + r0 + 8))*DM + n*HD + dd] = v1;
    }
}

// ---------------------------------------------------------------------------
// K4: h = query + av @ Wo + bo (fp32).  grid (32, 12)
// ---------------------------------------------------------------------------
__global__ void __launch_bounds__(256) proj_kernel(
    const float* __restrict__ Wo, const float* __restrict__ bo,
    const float* __restrict__ x)
{
    __shared__ float sA[16][65];
    __shared__ float sB[16][64];
    const int m0 = blockIdx.x * 64;
    const int o0 = blockIdx.y * 64;
    const int tid = threadIdx.x, tx = tid & 15, ty = tid >> 4;
    const int la_k = tid & 15, la_m = tid >> 4;
    float acc[4][4] = {};

    for (int kb = 0; kb < DM; kb += 16) {
        #pragma unroll
        for (int r = 0; r < 4; r++)
            sA[la_k][la_m + r*16] = g_av[(size_t)(m0 + la_m + r*16) * DM + kb + la_k];
        *(float4*)&sB[la_m][la_k*4] =
            *(const float4*)&Wo[(size_t)(kb + la_m) * DM + o0 + la_k*4];
        __syncthreads();
        #pragma unroll
        for (int kk = 0; kk < 16; kk++) {
            float a[4];
            #pragma unroll
            for (int q = 0; q < 4; q++) a[q] = sA[kk][ty*4 + q];
            float4 b4 = *(float4*)&sB[kk][tx*4];
            #pragma unroll
            for (int di = 0; di < 4; di++) {
                acc[di][0] += a[di]*b4.x; acc[di][1] += a[di]*b4.y;
                acc[di][2] += a[di]*b4.z; acc[di][3] += a[di]*b4.w;
            }
        }
        __syncthreads();
    }
    const int d0 = tx*4;
    #pragma unroll
    for (int di = 0; di < 4; di++) {
        int m = m0 + ty*4 + di;
        size_t ob = (size_t)m * DM + o0 + d0;
        float4 qv = *(const float4*)&x[ob];
        float4 v;
        v.x = acc[di][0] + bo[o0+d0+0] + qv.x;
        v.y = acc[di][1] + bo[o0+d0+1] + qv.y;
        v.z = acc[di][2] + bo[o0+d0+2] + qv.z;
        v.w = acc[di][3] + bo[o0+d0+3] + qv.w;
        *(float4*)&g_h[ob] = v;
    }
}

// ---------------------------------------------------------------------------
// K5: LayerNorm.  grid (2048), 256 threads
// ---------------------------------------------------------------------------
__global__ void __launch_bounds__(256) ln_kernel(
    const float* __restrict__ gamma, const float* __restrict__ beta,
    float* __restrict__ out)
{
    __shared__ float red[16];
    const int row = blockIdx.x;
    const int tid = threadIdx.x;
    const float* h = g_h + (size_t)row * DM;
    float v0 = h[tid], v1 = h[tid+256], v2 = h[tid+512];
    float s = v0+v1+v2, ss = v0*v0+v1*v1+v2*v2;
    #pragma unroll
    for (int o = 16; o >= 1; o >>= 1) {
        s  += __shfl_xor_sync(0xffffffffu, s,  o);
        ss += __shfl_xor_sync(0xffffffffu, ss, o);
    }
    if ((tid & 31) == 0) { red[tid>>5] = s; red[8 + (tid>>5)] = ss; }
    __syncthreads();
    if (tid < 32) {
        float a = (tid < 8)  ? red[tid]     : 0.f;
        float b = (tid < 8)  ? red[8+tid]   : 0.f;
        #pragma unroll
        for (int o = 4; o >= 1; o >>= 1) {
            a += __shfl_xor_sync(0xffffffffu, a, o);
            b += __shfl_xor_sync(0xffffffffu, b, o);
        }
        if (tid == 0) { red[0] = a; red[1] = b; }
    }
    __syncthreads();
    float mu  = red[0] * (1.f/DM);
    float var = red[1] * (1.f/DM) - mu*mu;
    float inv = rsqrtf(var + 1e-9f);
    out[(size_t)row*DM + tid]     = (v0 - mu)*inv*gamma[tid]     + beta[tid];
    out[(size_t)row*DM + tid+256] = (v1 - mu)*inv*gamma[tid+256] + beta[tid+256];
    out[(size_t)row*DM + tid+512] = (v2 - mu)*inv*gamma[tid+512] + beta[tid+512];
}

// ---------------------------------------------------------------------------
extern "C" void kernel_launch(void* const* d_in, const int* in_sizes, int n_in,
                              void* d_out, int out_size)
{
    const float* query = (const float*)d_in[0];
    const float* pe    = (const float*)d_in[1];
    const float* Wq    = (const float*)d_in[2];
    const float* Wk    = (const float*)d_in[3];
    const float* bk    = (const float*)d_in[4];
    const float* Wv    = (const float*)d_in[5];
    const float* bv    = (const float*)d_in[6];
    const float* rk    = (const float*)d_in[7];
    const float* rwb   = (const float*)d_in[8];
    const float* rrb   = (const float*)d_in[9];
    const float* Wo    = (const float*)d_in[10];
    const float* bo    = (const float*)d_in[11];
    const float* gamma = (const float*)d_in[12];
    const float* beta  = (const float*)d_in[13];
    float* out = (float*)d_out;

    static bool attr_set = false;
    if (!attr_set) {
        cudaFuncSetAttribute(attn_kernel,
            cudaFuncAttributeMaxDynamicSharedMemorySize, ATT_SMEM_BYTES);
        attr_set = true;
    }

    qkv_kernel<<<dim3(32,12,3), 256>>>(query, Wq, Wk, bk, Wv, bv, rwb, rrb);
    rhead_kernel<<<dim3(32,12), 256>>>(pe, rk);
    attn_kernel<<<dim3(16,24), 128, ATT_SMEM_BYTES>>>();
    proj_kernel<<<dim3(32,12), 256>>>(Wo, bo, query);
    ln_kernel<<<2048, 256>>>(gamma, beta, out);
}

// round 5
// speedup vs baseline: 4.4078x; 1.9379x over previous
#include <cuda_runtime.h>
#include <cuda_bf16.h>
#include <math.h>

#define BD   2
#define SEQ  1024
#define DM   768
#define NH   12
#define HD   64
#define GD   192
#define ATT_SCALE 0.125f

typedef __nv_bfloat16 bf16;

// ------------------------------ scratch ------------------------------------
__device__ __align__(16) bf16 g_qw[BD*NH*SEQ*HD];
__device__ __align__(16) bf16 g_qr[BD*NH*SEQ*HD];
__device__ __align__(16) bf16 g_k [BD*NH*SEQ*HD];
__device__ __align__(16) bf16 g_v [BD*NH*SEQ*HD];
__device__ __align__(16) bf16 g_rh[NH*2048*HD];
__device__ __align__(16) bf16 g_avh[BD*SEQ*DM];
__device__ __align__(16) bf16 g_avl[BD*SEQ*DM];
__device__ __align__(16) bf16 g_woh[DM*DM];
__device__ __align__(16) bf16 g_wol[DM*DM];
__device__ float g_h [BD*SEQ*DM];

// ------------------------------ helpers ------------------------------------
__device__ __forceinline__ unsigned pk(float lo, float hi) {
    __nv_bfloat162 h = __floats2bfloat162_rn(lo, hi);
    return *(unsigned*)&h;
}
__device__ __forceinline__ unsigned s2u(const void* p) {
    return (unsigned)__cvta_generic_to_shared(p);
}
__device__ __forceinline__ void ldm_x4(unsigned& r0, unsigned& r1, unsigned& r2, unsigned& r3, unsigned a) {
    asm volatile("ldmatrix.sync.aligned.m8n8.x4.shared.b16 {%0,%1,%2,%3},[%4];"
                 : "=r"(r0), "=r"(r1), "=r"(r2), "=r"(r3) : "r"(a));
}
__device__ __forceinline__ void ldm_x2(unsigned& r0, unsigned& r1, unsigned a) {
    asm volatile("ldmatrix.sync.aligned.m8n8.x2.shared.b16 {%0,%1},[%2];"
                 : "=r"(r0), "=r"(r1) : "r"(a));
}
__device__ __forceinline__ void ldm_x2t(unsigned& r0, unsigned& r1, unsigned a) {
    asm volatile("ldmatrix.sync.aligned.m8n8.x2.trans.shared.b16 {%0,%1},[%2];"
                 : "=r"(r0), "=r"(r1) : "r"(a));
}
__device__ __forceinline__ void mma_bf16(float* c, const unsigned* a, unsigned b0, unsigned b1) {
    asm volatile("mma.sync.aligned.m16n8k16.row.col.f32.bf16.bf16.f32 "
                 "{%0,%1,%2,%3},{%4,%5,%6,%7},{%8,%9},{%0,%1,%2,%3};"
                 : "+f"(c[0]), "+f"(c[1]), "+f"(c[2]), "+f"(c[3])
                 : "r"(a[0]), "r"(a[1]), "r"(a[2]), "r"(a[3]), "r"(b0), "r"(b1));
}

// 64x64 fp32 tile -> bf16 swizzled smem (128B rows, 16B chunk XOR swizzle)
__device__ __forceinline__ void load_conv_tile(bf16* dst, const float* src, int ld,
                                               int valid_rows, int tid) {
    #pragma unroll
    for (int it = 0; it < 4; it++) {
        int c = tid + it*128, row = c >> 3, ch = c & 7;
        uint4 w = make_uint4(0u,0u,0u,0u);
        if (row < valid_rows) {
            const float* p = src + (size_t)row*ld + ch*8;
            float4 u = *(const float4*)p;
            float4 v = *(const float4*)(p+4);
            w.x = pk(u.x,u.y); w.y = pk(u.z,u.w);
            w.z = pk(v.x,v.y); w.w = pk(v.z,v.w);
        }
        *(uint4*)((char*)dst + row*128 + ((ch ^ (row&7)) << 4)) = w;
    }
}
// 64x64 bf16 tile copy (arbitrary row stride in elements) -> swizzled smem
__device__ __forceinline__ void copy_bf16_tile(bf16* dst, const bf16* src, int ld, int tid) {
    #pragma unroll
    for (int it = 0; it < 4; it++) {
        int c = tid + it*128, row = c >> 3, ch = c & 7;
        uint4 v = *(const uint4*)(src + (size_t)row*ld + ch*8);
        *(uint4*)((char*)dst + row*128 + ((ch ^ (row&7)) << 4)) = v;
    }
}

// compute one 64x64 tile: c += A(sA) @ B(sB), warp w rows w*16..+15
__device__ __forceinline__ void mma_tile(float (*c)[4], const bf16* sA, const bf16* sB,
                                         int lane, int w) {
    unsigned a[4][4];
    int arow = w*16 + (lane & 15), csel = lane >> 4;
    #pragma unroll
    for (int ks = 0; ks < 4; ks++) {
        int ch = ks*2 + csel;
        ldm_x4(a[ks][0], a[ks][1], a[ks][2], a[ks][3],
               s2u((const char*)sA + arow*128 + ((ch ^ (arow&7)) << 4)));
    }
    #pragma unroll
    for (int nb = 0; nb < 8; nb++) {
        #pragma unroll
        for (int ks = 0; ks < 4; ks++) {
            int vrow = ks*16 + (lane & 15);
            unsigned b0, b1;
            ldm_x2t(b0, b1, s2u((const char*)sB + vrow*128 + ((nb ^ (vrow&7)) << 4)));
            mma_bf16(c[nb], a[ks], b0, b1);
        }
    }
}

// ---------------------------------------------------------------------------
// K0: split Wo into bf16 hi/lo.  grid 576, 256 thr
// ---------------------------------------------------------------------------
__global__ void __launch_bounds__(256) wo_prep(const float* __restrict__ Wo)
{
    int i = (blockIdx.x*256 + threadIdx.x) * 4;
    float4 v = *(const float4*)&Wo[i];
    unsigned h0 = pk(v.x, v.y), h1 = pk(v.z, v.w);
    __nv_bfloat162 a = *(__nv_bfloat162*)&h0, b = *(__nv_bfloat162*)&h1;
    unsigned l0 = pk(v.x - __low2float(a), v.y - __high2float(a));
    unsigned l1 = pk(v.z - __low2float(b), v.w - __high2float(b));
    *(uint2*)&g_woh[i] = make_uint2(h0, h1);
    *(uint2*)&g_wol[i] = make_uint2(l0, l1);
}

// ---------------------------------------------------------------------------
// K1: grouped QKV projection (bf16 MMA).  grid (32, 12, 3), 128 thr
// ---------------------------------------------------------------------------
__global__ void __launch_bounds__(128) qkv_kernel(
    const float* __restrict__ x,
    const float* __restrict__ Wq, const float* __restrict__ Wk, const float* __restrict__ bk,
    const float* __restrict__ Wv, const float* __restrict__ bv,
    const float* __restrict__ rwb, const float* __restrict__ rrb)
{
    __shared__ bf16 sA[64*64], sB[64*64];
    const int tid = threadIdx.x, lane = tid & 31, w = tid >> 5;
    const int m0 = blockIdx.x * 64;
    const int g  = blockIdx.y / 3, oo0 = (blockIdx.y % 3) * 64;
    const int z  = blockIdx.z;
    const float* W = ((z == 0) ? Wq : (z == 1) ? Wk : Wv) + g * GD * GD;
    float c[8][4] = {};

    for (int kb = 0; kb < GD; kb += 64) {
        __syncthreads();
        load_conv_tile(sA, x + (size_t)m0*DM + g*GD + kb, DM, 64, tid);
        load_conv_tile(sB, W + (size_t)kb*GD + oo0, GD, 64, tid);
        __syncthreads();
        mma_tile(c, sA, sB, lane, w);
    }

    const int n = blockIdx.y;                 // 3g + oo0/64
    const int o0g = g*GD + oo0;
    const int r0 = w*16 + (lane >> 2), q2 = 2*(lane & 3);
    const int b = m0 >> 10;
    const int s0 = (m0 & 1023) + r0;
    #pragma unroll
    for (int nb = 0; nb < 8; nb++) {
        int d = nb*8 + q2, bi = o0g + d;
        size_t ob0 = (((size_t)(b*NH + n))*SEQ + s0)*HD + d;
        size_t ob1 = ob0 + 8*HD;
        if (z == 0) {
            float w0 = rwb[bi], w1 = rwb[bi+1], r0b = rrb[bi], r1b = rrb[bi+1];
            *(unsigned*)&g_qw[ob0] = pk((c[nb][0]+w0)*ATT_SCALE, (c[nb][1]+w1)*ATT_SCALE);
            *(unsigned*)&g_qw[ob1] = pk((c[nb][2]+w0)*ATT_SCALE, (c[nb][3]+w1)*ATT_SCALE);
            *(unsigned*)&g_qr[ob0] = pk((c[nb][0]+r0b)*ATT_SCALE, (c[nb][1]+r1b)*ATT_SCALE);
            *(unsigned*)&g_qr[ob1] = pk((c[nb][2]+r0b)*ATT_SCALE, (c[nb][3]+r1b)*ATT_SCALE);
        } else if (z == 1) {
            float b0 = bk[bi], b1 = bk[bi+1];
            *(unsigned*)&g_k[ob0] = pk(c[nb][0]+b0, c[nb][1]+b1);
            *(unsigned*)&g_k[ob1] = pk(c[nb][2]+b0, c[nb][3]+b1);
        } else {
            float b0 = bv[bi], b1 = bv[bi+1];
            *(unsigned*)&g_v[ob0] = pk(c[nb][0]+b0, c[nb][1]+b1);
            *(unsigned*)&g_v[ob1] = pk(c[nb][2]+b0, c[nb][3]+b1);
        }
    }
}

// ---------------------------------------------------------------------------
// K2: r_head = position_embeds @ r_kernel (bf16 MMA).  grid (32, 12), 128 thr
// ---------------------------------------------------------------------------
__global__ void __launch_bounds__(128) rhead_kernel(
    const float* __restrict__ pe, const float* __restrict__ rk)
{
    __shared__ bf16 sA[64*64], sB[64*64];
    const int tid = threadIdx.x, lane = tid & 31, w = tid >> 5;
    const int t0 = blockIdx.x * 64;
    const int o0 = blockIdx.y * 64;
    const int vr = min(64, 2047 - t0);
    float c[8][4] = {};

    for (int kb = 0; kb < DM; kb += 64) {
        __syncthreads();
        load_conv_tile(sA, pe + (size_t)t0*DM + kb, DM, vr, tid);
        load_conv_tile(sB, rk + (size_t)kb*DM + o0, DM, 64, tid);
        __syncthreads();
        mma_tile(c, sA, sB, lane, w);
    }

    const int n = blockIdx.y;
    const int r0 = w*16 + (lane >> 2), q2 = 2*(lane & 3);
    #pragma unroll
    for (int nb = 0; nb < 8; nb++) {
        int d = nb*8 + q2;
        size_t ob0 = ((size_t)n*2048 + t0 + r0)*HD + d;
        *(unsigned*)&g_rh[ob0]        = pk(c[nb][0], c[nb][1]);
        *(unsigned*)&g_rh[ob0 + 8*HD] = pk(c[nb][2], c[nb][3]);
    }
}

// ---------------------------------------------------------------------------
// K3: flash attention, bf16 HMMA, pos' sliding-window ring. grid (16, 24), 128 thr
// ---------------------------------------------------------------------------
#define RING_PITCH 132
#define ATT_SMEM_BYTES (40960 + 64*RING_PITCH*4)

__device__ __forceinline__ void copy_tile64(bf16* dst, const bf16* src, int tid) {
    #pragma unroll
    for (int k = 0; k < 4; k++) {
        int c = tid + k*128, row = c >> 3, ch = c & 7;
        uint4 v = *(const uint4*)(src + (size_t)row*64 + ch*8);
        *(uint4*)((char*)dst + row*128 + ((ch ^ (row & 7)) << 4)) = v;
    }
}
__device__ __forceinline__ void load_rh_tile(bf16* dst, const bf16* src, int Tc, int tid) {
    #pragma unroll
    for (int k = 0; k < 4; k++) {
        int c = tid + k*128, row = c >> 3, ch = c & 7;
        int t = Tc + row;
        uint4 v = make_uint4(0u,0u,0u,0u);
        if (t < 2048) v = *(const uint4*)(src + (size_t)t*64 + ch*8);
        *(uint4*)((char*)dst + row*128 + ((ch ^ (row & 7)) << 4)) = v;
    }
}

__device__ __forceinline__ void pos_mma_ring(
    const bf16* sRh, float* ring, const unsigned (*qrA)[4],
    int Tc, int lane, int r0, int q2)
{
    #pragma unroll
    for (int nb = 0; nb < 8; nb++) {
        float pc[4] = {0.f, 0.f, 0.f, 0.f};
        int brow = nb*8 + (lane & 7);
        #pragma unroll
        for (int ks = 0; ks < 4; ks++) {
            int ch = ks*2 + ((lane >> 3) & 1);
            unsigned b0, b1;
            ldm_x2(b0, b1, s2u((const char*)sRh + brow*128 + ((ch ^ (brow & 7)) << 4)));
            mma_bf16(pc, qrA[ks], b0, b1);
        }
        int s0 = (Tc + nb*8 + q2) & 127;
        int s1 = (s0 + 1) & 127;
        ring[r0*RING_PITCH + s0]     = pc[0];
        ring[r0*RING_PITCH + s1]     = pc[1];
        ring[(r0+8)*RING_PITCH + s0] = pc[2];
        ring[(r0+8)*RING_PITCH + s1] = pc[3];
    }
}

__global__ void __launch_bounds__(128) attn_kernel()
{
    extern __shared__ char smc[];
    bf16*  sQw  = (bf16*)(smc);
    bf16*  sQr  = (bf16*)(smc + 8192);
    bf16*  sK   = (bf16*)(smc + 16384);
    bf16*  sRh  = (bf16*)(smc + 24576);
    bf16*  sV   = (bf16*)(smc + 32768);
    float* ring = (float*)(smc + 40960);

    const int tid = threadIdx.x, lane = tid & 31, w = tid >> 5;
    const int bn = blockIdx.y, n = bn % NH, b = bn / NH;
    const int i0 = blockIdx.x * 64;

    const bf16* qwB = g_qw + (size_t)bn * SEQ * HD;
    const bf16* qrB = g_qr + (size_t)bn * SEQ * HD;
    const bf16* kB  = g_k  + (size_t)bn * SEQ * HD;
    const bf16* vB  = g_v  + (size_t)bn * SEQ * HD;
    const bf16* rhB = g_rh + (size_t)n * 2048 * HD;

    copy_tile64(sQw, qwB + (size_t)i0*HD, tid);
    copy_tile64(sQr, qrB + (size_t)i0*HD, tid);
    load_rh_tile(sRh, rhB, 961 - i0, tid);
    __syncthreads();

    unsigned qwA[4][4], qrA[4][4];
    {
        int arow = w*16 + (lane & 15);
        int csel = lane >> 4;
        #pragma unroll
        for (int ks = 0; ks < 4; ks++) {
            int ch = ks*2 + csel;
            unsigned off = ((ch ^ (arow & 7)) << 4) + arow*128;
            ldm_x4(qwA[ks][0], qwA[ks][1], qwA[ks][2], qwA[ks][3], s2u((char*)sQw + off));
            ldm_x4(qrA[ks][0], qrA[ks][1], qrA[ks][2], qrA[ks][3], s2u((char*)sQr + off));
        }
    }

    const int r0 = w*16 + (lane >> 2);
    const int q2 = 2*(lane & 3);

    float o[8][4] = {};
    float mrow0 = -INFINITY, mrow1 = -INFINITY, lrow0 = 0.f, lrow1 = 0.f;

    pos_mma_ring(sRh, ring, qrA, 961 - i0, lane, r0, q2);

    for (int j0 = 0; j0 < SEQ; j0 += 64) {
        __syncthreads();
        copy_tile64(sK, kB + (size_t)j0*HD, tid);
        copy_tile64(sV, vB + (size_t)j0*HD, tid);
        const int Tc = 1025 + j0 - i0;
        load_rh_tile(sRh, rhB, Tc, tid);
        __syncthreads();

        float c[8][4] = {};
        #pragma unroll
        for (int nb = 0; nb < 8; nb++) {
            int brow = nb*8 + (lane & 7);
            #pragma unroll
            for (int ks = 0; ks < 4; ks++) {
                int ch = ks*2 + ((lane >> 3) & 1);
                unsigned b0, b1;
                ldm_x2(b0, b1, s2u((char*)sK + brow*128 + ((ch ^ (brow & 7)) << 4)));
                mma_bf16(c[nb], qwA[ks], b0, b1);
            }
        }
        pos_mma_ring(sRh, ring, qrA, Tc, lane, r0, q2);
        __syncthreads();

        #pragma unroll
        for (int nb = 0; nb < 8; nb++) {
            int jl = nb*8 + q2;
            int ta = 1024 + j0 + jl - (i0 + r0);
            c[nb][0] += ring[r0*RING_PITCH + (ta & 127)];
            c[nb][1] += ring[r0*RING_PITCH + ((ta + 1) & 127)];
            int tb = ta - 8;
            c[nb][2] += ring[(r0+8)*RING_PITCH + (tb & 127)];
            c[nb][3] += ring[(r0+8)*RING_PITCH + ((tb + 1) & 127)];
        }
        if (i0 == 0 && j0 == 960 && tid == 3) {
            float s = 0.f;
            #pragma unroll
            for (int d = 0; d < HD; d++)
                s += __bfloat162float(qrB[HD + d]) * __bfloat162float(rhB[d]);
            c[7][1] += s;
        }

        float mx0 = -INFINITY, mx1 = -INFINITY;
        #pragma unroll
        for (int nb = 0; nb < 8; nb++) {
            mx0 = fmaxf(mx0, fmaxf(c[nb][0], c[nb][1]));
            mx1 = fmaxf(mx1, fmaxf(c[nb][2], c[nb][3]));
        }
        mx0 = fmaxf(mx0, __shfl_xor_sync(0xffffffffu, mx0, 1));
        mx0 = fmaxf(mx0, __shfl_xor_sync(0xffffffffu, mx0, 2));
        mx1 = fmaxf(mx1, __shfl_xor_sync(0xffffffffu, mx1, 1));
        mx1 = fmaxf(mx1, __shfl_xor_sync(0xffffffffu, mx1, 2));
        float mn0 = fmaxf(mrow0, mx0), mn1 = fmaxf(mrow1, mx1);
        float sc0 = __expf(mrow0 - mn0), sc1 = __expf(mrow1 - mn1);
        mrow0 = mn0; mrow1 = mn1;
        float s0 = 0.f, s1 = 0.f;
        #pragma unroll
        for (int nb = 0; nb < 8; nb++) {
            c[nb][0] = __expf(c[nb][0] - mn0); s0 += c[nb][0];
            c[nb][1] = __expf(c[nb][1] - mn0); s0 += c[nb][1];
            c[nb][2] = __expf(c[nb][2] - mn1); s1 += c[nb][2];
            c[nb][3] = __expf(c[nb][3] - mn1); s1 += c[nb][3];
        }
        s0 += __shfl_xor_sync(0xffffffffu, s0, 1);
        s0 += __shfl_xor_sync(0xffffffffu, s0, 2);
        s1 += __shfl_xor_sync(0xffffffffu, s1, 1);
        s1 += __shfl_xor_sync(0xffffffffu, s1, 2);
        lrow0 = lrow0*sc0 + s0; lrow1 = lrow1*sc1 + s1;
        #pragma unroll
        for (int nb = 0; nb < 8; nb++) {
            o[nb][0] *= sc0; o[nb][1] *= sc0;
            o[nb][2] *= sc1; o[nb][3] *= sc1;
        }

        unsigned pa[4][4];
        #pragma unroll
        for (int ks = 0; ks < 4; ks++) {
            pa[ks][0] = pk(c[2*ks][0],   c[2*ks][1]);
            pa[ks][1] = pk(c[2*ks][2],   c[2*ks][3]);
            pa[ks][2] = pk(c[2*ks+1][0], c[2*ks+1][1]);
            pa[ks][3] = pk(c[2*ks+1][2], c[2*ks+1][3]);
        }
        #pragma unroll
        for (int nb = 0; nb < 8; nb++) {
            #pragma unroll
            for (int ks = 0; ks < 4; ks++) {
                int vrow = ks*16 + (lane & 15);
                unsigned b0, b1;
                ldm_x2t(b0, b1, s2u((char*)sV + vrow*128 + ((nb ^ (vrow & 7)) << 4)));
                mma_bf16(o[nb], pa[ks], b0, b1);
            }
        }
    }

    // epilogue: normalize + split into bf16 hi/lo
    float inv0 = 1.f / lrow0, inv1 = 1.f / lrow1;
    #pragma unroll
    for (int nb = 0; nb < 8; nb++) {
        int dd = nb*8 + q2;
        float a0 = o[nb][0]*inv0, a1 = o[nb][1]*inv0;
        float b0 = o[nb][2]*inv1, b1 = o[nb][3]*inv1;
        unsigned h0 = pk(a0, a1), h1 = pk(b0, b1);
        __nv_bfloat162 x0 = *(__nv_bfloat162*)&h0, x1 = *(__nv_bfloat162*)&h1;
        unsigned l0 = pk(a0 - __low2float(x0), a1 - __high2float(x0));
        unsigned l1 = pk(b0 - __low2float(x1), b1 - __high2float(x1));
        size_t ob0 = ((size_t)(b*SEQ + i0 + r0))*DM + n*HD + dd;
        size_t ob1 = ob0 + 8*DM;
        *(unsigned*)&g_avh[ob0] = h0;  *(unsigned*)&g_avl[ob0] = l0;
        *(unsigned*)&g_avh[ob1] = h1;  *(unsigned*)&g_avl[ob1] = l1;
    }
}

// ---------------------------------------------------------------------------
// K4: h = query + av @ Wo + bo  (split-bf16 MMA).  grid (32, 12), 128 thr
// ---------------------------------------------------------------------------
__global__ void __launch_bounds__(128) proj_kernel(
    const float* __restrict__ bo, const float* __restrict__ x)
{
    __shared__ bf16 sAh[64*64], sAl[64*64], sBh[64*64], sBl[64*64];
    const int tid = threadIdx.x, lane = tid & 31, w = tid >> 5;
    const int m0 = blockIdx.x * 64;
    const int o0 = blockIdx.y * 64;
    float c[8][4] = {};

    for (int kb = 0; kb < DM; kb += 64) {
        __syncthreads();
        copy_bf16_tile(sAh, g_avh + (size_t)m0*DM + kb, DM, tid);
        copy_bf16_tile(sAl, g_avl + (size_t)m0*DM + kb, DM, tid);
        copy_bf16_tile(sBh, g_woh + (size_t)kb*DM + o0, DM, tid);
        copy_bf16_tile(sBl, g_wol + (size_t)kb*DM + o0, DM, tid);
        __syncthreads();

        unsigned ah[4][4], al[4][4];
        int arow = w*16 + (lane & 15), csel = lane >> 4;
        #pragma unroll
        for (int ks = 0; ks < 4; ks++) {
            int ch = ks*2 + csel;
            unsigned off = arow*128 + ((ch ^ (arow&7)) << 4);
            ldm_x4(ah[ks][0], ah[ks][1], ah[ks][2], ah[ks][3], s2u((char*)sAh + off));
            ldm_x4(al[ks][0], al[ks][1], al[ks][2], al[ks][3], s2u((char*)sAl + off));
        }
        #pragma unroll
        for (int nb = 0; nb < 8; nb++) {
            #pragma unroll
            for (int ks = 0; ks < 4; ks++) {
                int vrow = ks*16 + (lane & 15);
                unsigned off = vrow*128 + ((nb ^ (vrow&7)) << 4);
                unsigned bh0, bh1, bl0, bl1;
                ldm_x2t(bh0, bh1, s2u((char*)sBh + off));
                ldm_x2t(bl0, bl1, s2u((char*)sBl + off));
                mma_bf16(c[nb], ah[ks], bh0, bh1);
                mma_bf16(c[nb], al[ks], bh0, bh1);
                mma_bf16(c[nb], ah[ks], bl0, bl1);
            }
        }
    }

    const int r0 = w*16 + (lane >> 2), q2 = 2*(lane & 3);
    #pragma unroll
    for (int nb = 0; nb < 8; nb++) {
        int col = o0 + nb*8 + q2;
        float b0 = bo[col], b1 = bo[col+1];
        size_t ob0 = (size_t)(m0 + r0)*DM + col;
        size_t ob1 = ob0 + 8*DM;
        float2 q0 = *(const float2*)&x[ob0];
        float2 q1 = *(const float2*)&x[ob1];
        *(float2*)&g_h[ob0] = make_float2(c[nb][0] + b0 + q0.x, c[nb][1] + b1 + q0.y);
        *(float2*)&g_h[ob1] = make_float2(c[nb][2] + b0 + q1.x, c[nb][3] + b1 + q1.y);
    }
}

// ---------------------------------------------------------------------------
// K5: LayerNorm.  grid (2048), 256 threads
// ---------------------------------------------------------------------------
__global__ void __launch_bounds__(256) ln_kernel(
    const float* __restrict__ gamma, const float* __restrict__ beta,
    float* __restrict__ out)
{
    __shared__ float red[16];
    const int row = blockIdx.x;
    const int tid = threadIdx.x;
    const float* h = g_h + (size_t)row * DM;
    float v0 = h[tid], v1 = h[tid+256], v2 = h[tid+512];
    float s = v0+v1+v2, ss = v0*v0+v1*v1+v2*v2;
    #pragma unroll
    for (int o = 16; o >= 1; o >>= 1) {
        s  += __shfl_xor_sync(0xffffffffu, s,  o);
        ss += __shfl_xor_sync(0xffffffffu, ss, o);
    }
    if ((tid & 31) == 0) { red[tid>>5] = s; red[8 + (tid>>5)] = ss; }
    __syncthreads();
    if (tid < 32) {
        float a = (tid < 8)  ? red[tid]     : 0.f;
        float b = (tid < 8)  ? red[8+tid]   : 0.f;
        #pragma unroll
        for (int o = 4; o >= 1; o >>= 1) {
            a += __shfl_xor_sync(0xffffffffu, a, o);
            b += __shfl_xor_sync(0xffffffffu, b, o);
        }
        if (tid == 0) { red[0] = a; red[1] = b; }
    }
    __syncthreads();
    float mu  = red[0] * (1.f/DM);
    float var = red[1] * (1.f/DM) - mu*mu;
    float inv = rsqrtf(var + 1e-9f);
    out[(size_t)row*DM + tid]     = (v0 - mu)*inv*gamma[tid]     + beta[tid];
    out[(size_t)row*DM + tid+256] = (v1 - mu)*inv*gamma[tid+256] + beta[tid+256];
    out[(size_t)row*DM + tid+512] = (v2 - mu)*inv*gamma[tid+512] + beta[tid+512];
}

// ---------------------------------------------------------------------------
extern "C" void kernel_launch(void* const* d_in, const int* in_sizes, int n_in,
                              void* d_out, int out_size)
{
    const float* query = (const float*)d_in[0];
    const float* pe    = (const float*)d_in[1];
    const float* Wq    = (const float*)d_in[2];
    const float* Wk    = (const float*)d_in[3];
    const float* bk    = (const float*)d_in[4];
    const float* Wv    = (const float*)d_in[5];
    const float* bv    = (const float*)d_in[6];
    const float* rk    = (const float*)d_in[7];
    const float* rwb   = (const float*)d_in[8];
    const float* rrb   = (const float*)d_in[9];
    const float* Wo    = (const float*)d_in[10];
    const float* bo    = (const float*)d_in[11];
    const float* gamma = (const float*)d_in[12];
    const float* beta  = (const float*)d_in[13];
    float* out = (float*)d_out;

    static bool attr_set = false;
    if (!attr_set) {
        cudaFuncSetAttribute(attn_kernel,
            cudaFuncAttributeMaxDynamicSharedMemorySize, ATT_SMEM_BYTES);
        attr_set = true;
    }

    wo_prep<<<DM*DM/1024, 256>>>(Wo);
    qkv_kernel<<<dim3(32,12,3), 128>>>(query, Wq, Wk, bk, Wv, bv, rwb, rrb);
    rhead_kernel<<<dim3(32,12), 128>>>(pe, rk);
    attn_kernel<<<dim3(16,24), 128, ATT_SMEM_BYTES>>>();
    proj_kernel<<<dim3(32,12), 128>>>(bo, query);
    ln_kernel<<<2048, 256>>>(gamma, beta, out);
}